// round 5
// baseline (speedup 1.0000x reference)
#include <cuda_runtime.h>
#include <cstdint>

// BilinearInteraction: out[b, p, :] = x[b, i_p, :] * (x[b, j_p, :] @ W)
//   x: [4096, 32, 64] f32, W: [64, 64] f32, out: [4096, 496, 64] f32
//   BPC=2 lane-packed GEMM (kills broadcast waste), W via L1-resident LDG,
//   row-sequential store streams (R2 write phase).

#define NF 32
#define ED 64
#define NP 496
#define NTHREADS 256
#define NBATCH 4096
#define BPC 2

// SMEM (float4 units): x tiles stride 516 (8256 B; %128 = 64 -> the two
// tiles sit at opposite 64B half-phases => dual-tile LDS is conflict-free),
// vid tiles same stride.
#define XS_STR4 516
#define VS_OFF4 (BPC * XS_STR4)             // 1032
#define SMEM_F4 (VS_OFF4 + BPC * XS_STR4)   // 2064 f4 = 33024 B

__global__ void __launch_bounds__(NTHREADS, 5)
bilinear_kernel(const float* __restrict__ x,
                const float* __restrict__ W,
                float* __restrict__ out)
{
    extern __shared__ float4 sm4[];

    const int tid    = threadIdx.x;
    const int b_base = blockIdx.x * BPC;

    // ---- Prologue: load 2 batches of x (1024 f4) into padded tiles ----
    {
        const float4* xg = (const float4*)(x + (size_t)b_base * (NF * ED));
#pragma unroll
        for (int k = 0; k < 4; k++) {
            const int idx = tid + k * NTHREADS;   // 0..1023
            const int t   = idx >> 9;             // batch tile
            const int off = idx & 511;
            sm4[t * XS_STR4 + off] = xg[idx];
        }
    }
    __syncthreads();

    // ---- GEMM: vid[g][f][e] = sum_d x[g][f][d] * W[d][e] ----
    // g = lane>>4 (batch), q = lane&15 (e-chunk 4q..4q+3), rows f = w + 8r.
    // x LDS.128: 2 distinct f4 (half-phase tiles) = 1 wf.
    // W LDG.128: 16 distinct f4 (dup across g) = 256B, L1-resident.
    {
        const int lane = tid & 31;
        const int w    = tid >> 5;
        const int g    = lane >> 4;
        const int q    = lane & 15;

        const float4* xt = sm4 + g * XS_STR4;
        const float4* W4 = (const float4*)W;

        float4 acc[4];
#pragma unroll
        for (int r = 0; r < 4; r++)
            acc[r] = make_float4(0.f, 0.f, 0.f, 0.f);

#pragma unroll 4
        for (int d4 = 0; d4 < 16; d4++) {
            float4 xv[4];
#pragma unroll
            for (int r = 0; r < 4; r++)
                xv[r] = xt[(w + 8 * r) * 16 + d4];

#pragma unroll
            for (int dd = 0; dd < 4; dd++) {
                const float4 wv = W4[(4 * d4 + dd) * 16 + q];
#pragma unroll
                for (int r = 0; r < 4; r++) {
                    const float xs = (dd == 0) ? xv[r].x :
                                     (dd == 1) ? xv[r].y :
                                     (dd == 2) ? xv[r].z : xv[r].w;
                    acc[r].x = fmaf(xs, wv.x, acc[r].x);
                    acc[r].y = fmaf(xs, wv.y, acc[r].y);
                    acc[r].z = fmaf(xs, wv.z, acc[r].z);
                    acc[r].w = fmaf(xs, wv.w, acc[r].w);
                }
            }
        }

        float4* vt = sm4 + VS_OFF4 + g * XS_STR4;
#pragma unroll
        for (int r = 0; r < 4; r++)
            vt[(w + 8 * r) * 16 + q] = acc[r];
    }
    __syncthreads();

    // ---- Write phase (R2 structure, per batch): row-sequential stores ----
    // Warp w owns rows {w, 30-w, 15-w, 15+w} (warp 0: {0, 30, 15}).
    {
        const int w    = tid >> 5;
        const int lane = tid & 31;
        const int v    = lane & 15;
        const int h    = lane >> 4;

        int rows[4];
        int nrows;
        if (w == 0) {
            rows[0] = 0; rows[1] = 30; rows[2] = 15; rows[3] = 0;
            nrows = 3;
        } else {
            rows[0] = w; rows[1] = 30 - w; rows[2] = 15 - w; rows[3] = 15 + w;
            nrows = 4;
        }

#pragma unroll
        for (int bt = 0; bt < BPC; bt++) {
            const float4* xs4  = sm4 + bt * XS_STR4;
            const float4* vs4  = sm4 + VS_OFF4 + bt * XS_STR4;
            float4*       out4 = (float4*)(out + (size_t)(b_base + bt) * (NP * ED));

#pragma unroll
            for (int r = 0; r < 4; r++) {
                if (r >= nrows) break;
                const int i = rows[r];
                const float4 a  = xs4[i * 16 + v];
                const int cnt   = 31 - i;
                const int iters = (cnt + 1) >> 1;
                const int p0    = (i * (63 - i)) >> 1;

#pragma unroll 2
                for (int t = 0; t < iters; t++) {
                    const int j = i + 1 + 2 * t + h;
                    if (j < NF) {
                        const float4 c = vs4[j * 16 + v];
                        const int p = p0 + (j - i - 1);
                        float4 rr;
                        rr.x = a.x * c.x;
                        rr.y = a.y * c.y;
                        rr.z = a.z * c.z;
                        rr.w = a.w * c.w;
                        out4[p * 16 + v] = rr;
                    }
                }
            }
        }
    }
}

extern "C" void kernel_launch(void* const* d_in, const int* in_sizes, int n_in,
                              void* d_out, int out_size)
{
    const float* x = (const float*)d_in[0];
    const float* W = (const float*)d_in[1];
    float*       o = (float*)d_out;

    cudaFuncSetAttribute(bilinear_kernel,
                         cudaFuncAttributeMaxDynamicSharedMemorySize,
                         SMEM_F4 * 16);
    bilinear_kernel<<<NBATCH / BPC, NTHREADS, SMEM_F4 * 16>>>(x, W, o);
}

// round 6
// speedup vs baseline: 1.2840x; 1.2840x over previous
#include <cuda_runtime.h>
#include <cstdint>

// BilinearInteraction: out[b, p, :] = x[b, i_p, :] * (x[b, j_p, :] @ W)
//   x: [4096, 32, 64] f32, W: [64, 64] f32, out: [4096, 496, 64] f32
//   R2 frame (6 CTAs/SM, row-sequential stores) with:
//   - GEMM relayout: 96 L1 wavefronts/warp instead of 192
//   - W loaded via cp.async.bulk (no l1tex cost)
//   - xs padded to 17 float4/row to de-conflict 4-row LDS gathers

#define NF 32
#define ED 64
#define NP 496
#define NTHREADS 256
#define NBATCH 4096
#define XSTR 17                   // xs row stride in float4

__device__ __forceinline__ unsigned smem_u32(const void* p) {
    unsigned a;
    asm("{ .reg .u64 t; cvta.to.shared.u64 t, %1; cvt.u32.u64 %0, t; }"
        : "=r"(a) : "l"(p));
    return a;
}

__global__ void __launch_bounds__(NTHREADS, 6)
bilinear_kernel(const float* __restrict__ x,
                const float* __restrict__ W,
                float* __restrict__ out)
{
    __shared__ float4 xs4[NF * XSTR];            // 8704 B (padded)
    __shared__ float4 vs4[NF * (ED / 4)];        // 8192 B
    __shared__ float4 Ws4[ED * (ED / 4)];        // 16384 B
    __shared__ __align__(8) unsigned long long mbar;

    const int b   = blockIdx.x;
    const int tid = threadIdx.x;

    // ---- mbarrier init, then W via 1D bulk copy (async proxy, no l1tex) ----
    if (tid == 0) {
        asm volatile("mbarrier.init.shared.b64 [%0], 1;"
                     :: "r"(smem_u32(&mbar)) : "memory");
    }
    __syncthreads();
    if (tid == 0) {
        const unsigned mb = smem_u32(&mbar);
        asm volatile("mbarrier.arrive.expect_tx.shared.b64 _, [%0], %1;"
                     :: "r"(mb), "r"(16384u) : "memory");
        asm volatile(
            "cp.async.bulk.shared::cluster.global.mbarrier::complete_tx::bytes "
            "[%0], [%1], %2, [%3];"
            :: "r"(smem_u32(Ws4)), "l"(W), "r"(16384u), "r"(mb) : "memory");
    }

    // ---- x prologue: padded copy (64 LDG wf + 64 STS wf per CTA) ----
    {
        const float4* xg = (const float4*)(x + (size_t)b * (NF * ED));
#pragma unroll
        for (int k = 0; k < 2; k++) {
            const int idx = tid + k * NTHREADS;   // 0..511
            const int row = idx >> 4;
            const int col = idx & 15;
            xs4[row * XSTR + col] = xg[idx];
        }
    }
    __syncthreads();

    // ---- wait for W (acquire) ----
    {
        const unsigned mb = smem_u32(&mbar);
        unsigned done;
        asm volatile(
            "{\n\t.reg .pred p;\n\t"
            "mbarrier.try_wait.parity.acquire.cta.shared::cta.b64 p, [%1], 0;\n\t"
            "selp.b32 %0, 1, 0, p;\n\t}"
            : "=r"(done) : "r"(mb) : "memory");
        while (!done) {
            asm volatile(
                "{\n\t.reg .pred p;\n\t"
                "mbarrier.try_wait.parity.acquire.cta.shared::cta.b64 p, [%1], 0, 0x989680;\n\t"
                "selp.b32 %0, 1, 0, p;\n\t}"
                : "=r"(done) : "r"(mb) : "memory");
        }
    }

    // ---- GEMM: vid[f][e] = sum_d x[f][d] * W[d][e] ----
    // Warp w: wr = w&3 (row block 8wr..8wr+7), half = w>>2 (e-f4 cols 8h..8h+7).
    // Lane: fi = lane>>3 (4 rows), ci = lane&7 (8 cols).
    // Thread: rows f0 = 8wr+fi, f1 = f0+4; col c = 8*half+ci.
    // x LDS.128: 4 distinct f4, bank-shifted via XSTR=17 -> 1 wf. (32/warp)
    // W LDS.128: 8 contiguous f4 = 128 B -> 1 wf.              (64/warp)
    {
        const int w    = tid >> 5;
        const int lane = tid & 31;
        const int wr   = w & 3;
        const int half = w >> 2;
        const int fi   = lane >> 3;
        const int ci   = lane & 7;
        const int f0   = 8 * wr + fi;
        const int c    = 8 * half + ci;

        float4 acc0 = make_float4(0.f, 0.f, 0.f, 0.f);
        float4 acc1 = make_float4(0.f, 0.f, 0.f, 0.f);

#pragma unroll 4
        for (int d4 = 0; d4 < 16; d4++) {
            const float4 xv0 = xs4[f0 * XSTR + d4];
            const float4 xv1 = xs4[(f0 + 4) * XSTR + d4];
#pragma unroll
            for (int dd = 0; dd < 4; dd++) {
                const float4 wv = Ws4[(4 * d4 + dd) * 16 + c];
                const float xa = (dd == 0) ? xv0.x : (dd == 1) ? xv0.y :
                                 (dd == 2) ? xv0.z : xv0.w;
                const float xb = (dd == 0) ? xv1.x : (dd == 1) ? xv1.y :
                                 (dd == 2) ? xv1.z : xv1.w;
                acc0.x = fmaf(xa, wv.x, acc0.x);
                acc0.y = fmaf(xa, wv.y, acc0.y);
                acc0.z = fmaf(xa, wv.z, acc0.z);
                acc0.w = fmaf(xa, wv.w, acc0.w);
                acc1.x = fmaf(xb, wv.x, acc1.x);
                acc1.y = fmaf(xb, wv.y, acc1.y);
                acc1.z = fmaf(xb, wv.z, acc1.z);
                acc1.w = fmaf(xb, wv.w, acc1.w);
            }
        }
        vs4[f0 * 16 + c]       = acc0;
        vs4[(f0 + 4) * 16 + c] = acc1;
    }
    __syncthreads();

    // ---- Write phase (R2 structure): row-sequential stores ----
    // Warp w owns rows {w, 30-w, 15-w, 15+w} (warp 0: {0, 30, 15}).
    {
        const int w    = tid >> 5;
        const int lane = tid & 31;
        const int v    = lane & 15;
        const int h    = lane >> 4;

        float4* out4 = (float4*)(out + (size_t)b * (NP * ED));

        int rows[4];
        int nrows;
        if (w == 0) {
            rows[0] = 0; rows[1] = 30; rows[2] = 15; rows[3] = 0;
            nrows = 3;
        } else {
            rows[0] = w; rows[1] = 30 - w; rows[2] = 15 - w; rows[3] = 15 + w;
            nrows = 4;
        }

#pragma unroll
        for (int r = 0; r < 4; r++) {
            if (r >= nrows) break;
            const int i = rows[r];
            const float4 a  = xs4[i * XSTR + v];
            const int cnt   = 31 - i;
            const int iters = (cnt + 1) >> 1;
            const int p0    = (i * (63 - i)) >> 1;

#pragma unroll 2
            for (int t = 0; t < iters; t++) {
                const int j = i + 1 + 2 * t + h;
                if (j < NF) {
                    const float4 cvv = vs4[j * 16 + v];
                    const int p = p0 + (j - i - 1);
                    float4 rr;
                    rr.x = a.x * cvv.x;
                    rr.y = a.y * cvv.y;
                    rr.z = a.z * cvv.z;
                    rr.w = a.w * cvv.w;
                    out4[p * 16 + v] = rr;
                }
            }
        }
    }
}

extern "C" void kernel_launch(void* const* d_in, const int* in_sizes, int n_in,
                              void* d_out, int out_size)
{
    const float* x = (const float*)d_in[0];
    const float* W = (const float*)d_in[1];
    float*       o = (float*)d_out;
    bilinear_kernel<<<NBATCH, NTHREADS>>>(x, W, o);
}